// round 5
// baseline (speedup 1.0000x reference)
#include <cuda_runtime.h>
#include <cstdint>

#define T_ 512
#define B_ 256
#define D_ 128
#define H_ 256
#define P_ 128
#define M_ (T_*B_)
#define NBLK 128
#define NTHR 256
#define BH_ (B_*H_)
#define CLUSTER_N 8

typedef unsigned long long ull;

// ---------------- scratch ---------------------------------------------------
__device__ float g_A[(size_t)T_*B_*P_];   // precomputed x-part of distance
__device__ float g_xsq[M_];
__device__ float g_psum[P_];

// ---------------- f32x2 / ptx helpers --------------------------------------
__device__ __forceinline__ ull pack2(float lo, float hi) {
    ull r; asm("mov.b64 %0, {%1, %2};" : "=l"(r) : "f"(lo), "f"(hi)); return r;
}
__device__ __forceinline__ void unpack2(ull v, float& lo, float& hi) {
    asm("mov.b64 {%0, %1}, %2;" : "=f"(lo), "=f"(hi) : "l"(v));
}
__device__ __forceinline__ ull fma2(ull a, ull b, ull c) {
    ull d; asm("fma.rn.f32x2 %0, %1, %2, %3;" : "=l"(d) : "l"(a), "l"(b), "l"(c));
    return d;
}
__device__ __forceinline__ float sigf(float x) {
    return __fdividef(1.f, 1.f + __expf(-x));
}
__device__ __forceinline__ float tanh_fast(float x) {
    float e = __expf(2.f * x);
    return 1.f - __fdividef(2.f, e + 1.f);
}
__device__ __forceinline__ uint32_t smem_u32(const void* p) {
    uint32_t a;
    asm("{ .reg .u64 t; cvta.to.shared.u64 t, %1; cvt.u32.u64 %0, t; }"
        : "=r"(a) : "l"(p));
    return a;
}
__device__ __forceinline__ uint32_t mapa_u32(uint32_t a, uint32_t rank) {
    uint32_t d;
    asm("mapa.shared::cluster.u32 %0, %1, %2;" : "=r"(d) : "r"(a), "r"(rank));
    return d;
}
#define CLUSTER_ARRIVE() asm volatile("barrier.cluster.arrive.aligned;" ::: "memory")
#define CLUSTER_WAIT()   asm volatile("barrier.cluster.wait.aligned;" ::: "memory")

// ---------------- precompute: row norms of x -------------------------------
__global__ void xsq_kernel(const float* __restrict__ x) {
    int warp = (blockIdx.x * blockDim.x + threadIdx.x) >> 5;
    int lane = threadIdx.x & 31;
    if (warp >= M_) return;
    const float* row = x + (size_t)warp * D_;
    float s = 0.f;
#pragma unroll
    for (int i = 0; i < 4; i++) { float v = row[lane + 32*i]; s += v*v; }
#pragma unroll
    for (int o = 16; o; o >>= 1) s += __shfl_down_sync(0xffffffffu, s, o);
    if (lane == 0) g_xsq[warp] = s;
}

// ---------------- precompute: full row norms of prototypes -----------------
__global__ void psum_kernel(const float* __restrict__ proto) {
    int p = threadIdx.x;
    if (p >= P_) return;
    const float* row = proto + (size_t)p * (D_ + H_);
    float s = 0.f;
    for (int i = 0; i < D_ + H_; i++) { float v = row[i]; s += v*v; }
    g_psum[p] = s;
}

// ---------------- precompute GEMM: A[t,b,p] = xsq + psum - 2*x.px ----------
__global__ void agemm_kernel(const float* __restrict__ x,
                             const float* __restrict__ proto) {
    __shared__ float sX[64][33];
    __shared__ float sP[32][132];
    const int tid = threadIdx.x;
    const int tx = tid & 31;
    const int ty = tid >> 5;
    const int m0 = blockIdx.x * 64;

    float acc[8][4];
#pragma unroll
    for (int r = 0; r < 8; r++)
#pragma unroll
        for (int q = 0; q < 4; q++) acc[r][q] = 0.f;

    for (int k0 = 0; k0 < D_; k0 += 32) {
#pragma unroll
        for (int i = 0; i < 8; i++) {
            int e = tid + i * 256;
            int r = e >> 5, c = e & 31;
            sX[r][c] = x[(size_t)(m0 + r) * D_ + k0 + c];
        }
#pragma unroll
        for (int i = 0; i < 16; i++) {
            int e = tid + i * 256;
            int p = e >> 5, c = e & 31;
            sP[c][p] = proto[(size_t)p * (D_ + H_) + k0 + c];
        }
        __syncthreads();
#pragma unroll
        for (int kc = 0; kc < 32; kc++) {
            float4 b4 = *(const float4*)&sP[kc][tx * 4];
#pragma unroll
            for (int r = 0; r < 8; r++) {
                float a = sX[ty * 8 + r][kc];
                acc[r][0] += a * b4.x; acc[r][1] += a * b4.y;
                acc[r][2] += a * b4.z; acc[r][3] += a * b4.w;
            }
        }
        __syncthreads();
    }
#pragma unroll
    for (int r = 0; r < 8; r++) {
        int row = m0 + ty * 8 + r;
        float xs = g_xsq[row];
        float4 o;
        o.x = xs + g_psum[tx*4+0] - 2.f * acc[r][0];
        o.y = xs + g_psum[tx*4+1] - 2.f * acc[r][1];
        o.z = xs + g_psum[tx*4+2] - 2.f * acc[r][2];
        o.w = xs + g_psum[tx*4+3] - 2.f * acc[r][3];
        *(float4*)&g_A[(size_t)row * P_ + tx * 4] = o;
    }
}

// ---------------- main persistent recurrent kernel (8-CTA cluster) ---------
// smem floats:
//   s_pH  [16][260]   4160   off 0
//   s_W   [128][128] 16384   off 4160
//   s_h   [16][260]   4160   off 20544
//   s_kT2 [128][16][2] 4096  off 24704
//   s_hsq [16]          16   off 28800
#define SMEM_FLOATS 28816
#define SH_BYTE_OFF   (20544u * 4u)
#define SKT_BYTE_OFF  (24704u * 4u)

__global__ void __launch_bounds__(NTHR, 1) __cluster_dims__(CLUSTER_N, 1, 1)
qlstm_main(const float* __restrict__ proto,
           const float* __restrict__ Wf_, const float* __restrict__ bf_,
           const float* __restrict__ Wi_, const float* __restrict__ bi_,
           const float* __restrict__ Wg_, const float* __restrict__ bg_,
           const float* __restrict__ Wo_, const float* __restrict__ bo_,
           float* __restrict__ out) {
    extern __shared__ float sm[];
    float* s_pH  = sm;                    // 16*260
    float* s_W   = s_pH + 16 * 260;       // [p][unit*4+gate]
    float* s_h   = s_W + 128 * 128;       // full h tile [16][260]
    float* s_kT2 = s_h + 16 * 260;        // [p_global][b][2] duplicated k
    float* s_hsq = s_kT2 + 4096;          // 16

    const int tid = threadIdx.x;
    uint32_t sub_u, bt_u;
    asm("mov.u32 %0, %%cluster_ctarank;" : "=r"(sub_u));
    asm("mov.u32 %0, %%clusterid.x;"     : "=r"(bt_u));
    const int sub = (int)sub_u;   // p-tile (phase1) / unit-chunk (phase2)
    const int bt  = (int)bt_u;    // batch tile 0..15

    // phase-1 mapping
    const int bl1 = tid >> 4;
    const int pl1 = tid & 15;
    // phase-2 mapping: warp covers 8 units x 8 rows; lane = 2 rows x 1 unit
    const int w    = tid >> 5;
    const int lane = tid & 31;
    const int rh   = w >> 2;
    const int uq   = w & 3;
    const int unit = uq * 8 + (lane & 7);
    const int rr   = lane >> 3;
    const int row0 = rh * 8 + rr * 2;     // even
    const int gu   = sub * 32 + unit;
    const int idx0 = (bt * 16 + row0) * H_ + gu;
    const int idx1 = idx0 + H_;

    // ---- persistent SMEM fills ----
    for (int i = tid; i < 16 * 256; i += NTHR) {
        int pl = i >> 8, j = i & 255;
        s_pH[pl * 260 + j] = proto[(size_t)(sub * 16 + pl) * (D_ + H_) + D_ + j];
    }
#pragma unroll
    for (int g = 0; g < 4; g++) {
        const float* Wp = (g == 0) ? Wf_ : (g == 1) ? Wi_ : (g == 2) ? Wg_ : Wo_;
        for (int i = tid; i < 128 * 32; i += NTHR) {
            int p = i & 127, ul = i >> 7;
            s_W[p * 128 + ul * 4 + g] = Wp[(size_t)(sub * 32 + ul) * P_ + p];
        }
    }
    for (int i = tid; i < 16 * 260; i += NTHR) s_h[i] = 0.f;
    const ull bfi = pack2(bf_[gu], bi_[gu]);
    const ull bgo = pack2(bg_[gu], bo_[gu]);

    // ---- precompute remote DSMEM addresses (hoisted mapa) ----
    uint32_t sbase = smem_u32(sm);
    const uint32_t my_kt_off = SKT_BYTE_OFF + (uint32_t)(((sub*16 + pl1)*16 + bl1) * 8);
    const uint32_t my_h0_off = SH_BYTE_OFF  + (uint32_t)((row0 * 260 + gu) * 4);
    uint32_t kt_addr[CLUSTER_N], h0_addr[CLUSTER_N];
#pragma unroll
    for (int r = 0; r < CLUSTER_N; r++) {
        uint32_t rb = mapa_u32(sbase, (uint32_t)r);
        kt_addr[r] = rb + my_kt_off;
        h0_addr[r] = rb + my_h0_off;
    }

    float c0 = 0.f, c1 = 0.f, h0v = 0.f, h1v = 0.f;

    __syncthreads();
    CLUSTER_ARRIVE();
    CLUSTER_WAIT();   // all CTAs initialized (h zeros, W, pH)

    const size_t OUT_H = (size_t)T_ * BH_;
    const size_t a_base = (size_t)(bt * 16 + bl1) * P_ + sub * 16 + pl1;
    float a_cur = __ldcg(&g_A[a_base]);

#pragma unroll 1
    for (int t = 0; t < T_; t++) {
        // ================= phase 1: k tile (16 b x 16 p) =================
        {
            // hsq: 16-lane cooperative reduction per row
            float s = 0.f;
            const float4* hp4 = (const float4*)&s_h[bl1 * 260 + pl1 * 16];
#pragma unroll
            for (int q = 0; q < 4; q++) {
                float4 v = hp4[q];
                s += v.x*v.x + v.y*v.y + v.z*v.z + v.w*v.w;
            }
#pragma unroll
            for (int o = 8; o; o >>= 1)
                s += __shfl_down_sync(0xffffffffu, s, o, 16);
            if (pl1 == 0) s_hsq[bl1] = s;

            // dot(h_row, pH_row) with packed f32x2
            ull acc2a = 0ull, acc2b = 0ull;
            const float* hp = &s_h[bl1 * 260];
            const float* pp = &s_pH[pl1 * 260];
#pragma unroll 8
            for (int j = 0; j < 256; j += 4) {
                ulonglong2 hv = *(const ulonglong2*)(hp + j);
                ulonglong2 pv = *(const ulonglong2*)(pp + j);
                acc2a = fma2(hv.x, pv.x, acc2a);
                acc2b = fma2(hv.y, pv.y, acc2b);
            }
            float dx, dy, dz, dw;
            unpack2(acc2a, dx, dy); unpack2(acc2b, dz, dw);
            float dot = (dx + dy) + (dz + dw);
            __syncthreads();   // s_hsq ready
            float d2 = a_cur + s_hsq[bl1] - 2.f * dot;
            float kk = __expf(-d2);
            ull kk2 = pack2(kk, kk);
            // broadcast duplicated k pair into every CTA's s_kT2
#pragma unroll
            for (int r = 0; r < CLUSTER_N; r++)
                asm volatile("st.shared::cluster.b64 [%0], %1;"
                             :: "r"(kt_addr[r]), "l"(kk2) : "memory");
        }
        CLUSTER_ARRIVE();
        // prefetch next step's A while the barrier drains
        {
            int tn = (t + 1 < T_) ? (t + 1) : (T_ - 1);
            a_cur = __ldcg(&g_A[(size_t)tn * B_ * P_ + a_base]);
        }
        CLUSTER_WAIT();

        // ================= phase 2: gates + state update =================
        {
            ull afi0 = bfi, ago0 = bgo, afi1 = bfi, ago1 = bgo;
            const float* kbase = &s_kT2[row0 * 2];
#pragma unroll 8
            for (int p = 0; p < 128; p++) {
                ulonglong2 w2 = *(const ulonglong2*)&s_W[p * 128 + unit * 4];
                ulonglong2 kk = *(const ulonglong2*)(kbase + p * 32);
                afi0 = fma2(kk.x, w2.x, afi0);
                ago0 = fma2(kk.x, w2.y, ago0);
                afi1 = fma2(kk.y, w2.x, afi1);
                ago1 = fma2(kk.y, w2.y, ago1);
            }
            float vf, vi, vg, vo;
            unpack2(afi0, vf, vi); unpack2(ago0, vg, vo);
            {
                float f = sigf(vf), ii = sigf(vi), gg = tanh_fast(vg), o = sigf(vo);
                c0 = f * c0 + ii * gg;
                h0v = o * tanh_fast(c0);
            }
            unpack2(afi1, vf, vi); unpack2(ago1, vg, vo);
            {
                float f = sigf(vf), ii = sigf(vi), gg = tanh_fast(vg), o = sigf(vo);
                c1 = f * c1 + ii * gg;
                h1v = o * tanh_fast(c1);
            }
            // broadcast h chunk into every CTA's s_h (row1 = row0+1 -> +1040B)
#pragma unroll
            for (int r = 0; r < CLUSTER_N; r++) {
                asm volatile("st.shared::cluster.b32 [%0], %1;"
                             :: "r"(h0_addr[r]), "f"(h0v) : "memory");
                asm volatile("st.shared::cluster.b32 [%0+1040], %1;"
                             :: "r"(h0_addr[r]), "f"(h1v) : "memory");
            }
            out[(size_t)t * BH_ + idx0] = h0v;
            out[(size_t)t * BH_ + idx1] = h1v;
        }
        CLUSTER_ARRIVE();
        CLUSTER_WAIT();
    }

    // final hx / cx
    out[OUT_H + idx0] = h0v;
    out[OUT_H + BH_ + idx0] = c0;
    out[OUT_H + idx1] = h1v;
    out[OUT_H + BH_ + idx1] = c1;
}

// ---------------- launch ----------------------------------------------------
extern "C" void kernel_launch(void* const* d_in, const int* in_sizes, int n_in,
                              void* d_out, int out_size) {
    const float* x     = (const float*)d_in[0];
    const float* proto = (const float*)d_in[1];
    const float* Wf    = (const float*)d_in[2];
    const float* bf    = (const float*)d_in[3];
    const float* Wi    = (const float*)d_in[4];
    const float* bi    = (const float*)d_in[5];
    const float* Wg    = (const float*)d_in[6];
    const float* bg    = (const float*)d_in[7];
    const float* Wo    = (const float*)d_in[8];
    const float* bo    = (const float*)d_in[9];
    float* out = (float*)d_out;

    const int smem_bytes = SMEM_FLOATS * (int)sizeof(float);
    cudaFuncSetAttribute(qlstm_main, cudaFuncAttributeMaxDynamicSharedMemorySize,
                         smem_bytes);

    xsq_kernel<<<M_ / 8, 256>>>(x);
    psum_kernel<<<1, 128>>>(proto);
    agemm_kernel<<<M_ / 64, 256>>>(x, proto);
    qlstm_main<<<NBLK, NTHR, smem_bytes>>>(proto, Wf, bf, Wi, bi, Wg, bg, Wo, bo, out);
}

// round 6
// speedup vs baseline: 1.5728x; 1.5728x over previous
#include <cuda_runtime.h>
#include <cstdint>

#define T_ 512
#define B_ 256
#define D_ 128
#define H_ 256
#define P_ 128
#define M_ (T_*B_)
#define NBLK 128
#define NTHR 256
#define BH_ (B_*H_)

typedef unsigned long long ull;

// ---------------- scratch ---------------------------------------------------
__device__ float g_A[(size_t)T_*B_*P_];   // precomputed x-part of distance
__device__ float g_xsq[M_];
__device__ float g_psum[P_];
__device__ float g_h[BH_];
__device__ float g_kT[16*128*16];         // [group][p][b]
__device__ unsigned int g_cnt[2*16*32];   // 2 barriers x 16 groups, 128B apart

// ---------------- f32x2 helpers --------------------------------------------
__device__ __forceinline__ ull pack2(float lo, float hi) {
    ull r; asm("mov.b64 %0, {%1, %2};" : "=l"(r) : "f"(lo), "f"(hi)); return r;
}
__device__ __forceinline__ void unpack2(ull v, float& lo, float& hi) {
    asm("mov.b64 {%0, %1}, %2;" : "=f"(lo), "=f"(hi) : "l"(v));
}
__device__ __forceinline__ ull fma2(ull a, ull b, ull c) {
    ull d; asm("fma.rn.f32x2 %0, %1, %2, %3;" : "=l"(d) : "l"(a), "l"(b), "l"(c));
    return d;
}
__device__ __forceinline__ float sigf(float x) {
    return __fdividef(1.f, 1.f + __expf(-x));
}
__device__ __forceinline__ float tanh_fast(float x) {
    float e = __expf(2.f * x);
    return 1.f - __fdividef(2.f, e + 1.f);
}

// ---------------- precompute: row norms of x -------------------------------
__global__ void xsq_kernel(const float* __restrict__ x) {
    int warp = (blockIdx.x * blockDim.x + threadIdx.x) >> 5;
    int lane = threadIdx.x & 31;
    if (warp >= M_) return;
    const float* row = x + (size_t)warp * D_;
    float s = 0.f;
#pragma unroll
    for (int i = 0; i < 4; i++) { float v = row[lane + 32*i]; s += v*v; }
#pragma unroll
    for (int o = 16; o; o >>= 1) s += __shfl_down_sync(0xffffffffu, s, o);
    if (lane == 0) g_xsq[warp] = s;
}

// ---------------- precompute: full row norms of prototypes -----------------
__global__ void psum_kernel(const float* __restrict__ proto) {
    int p = threadIdx.x;
    if (p >= P_) return;
    const float* row = proto + (size_t)p * (D_ + H_);
    float s = 0.f;
    for (int i = 0; i < D_ + H_; i++) { float v = row[i]; s += v*v; }
    g_psum[p] = s;
}

// ---------------- precompute GEMM: A[t,b,p] = xsq + psum - 2*x.px ----------
__global__ void agemm_kernel(const float* __restrict__ x,
                             const float* __restrict__ proto) {
    __shared__ float sX[64][33];
    __shared__ float sP[32][132];
    const int tid = threadIdx.x;
    const int tx = tid & 31;
    const int ty = tid >> 5;
    const int m0 = blockIdx.x * 64;

    float acc[8][4];
#pragma unroll
    for (int r = 0; r < 8; r++)
#pragma unroll
        for (int q = 0; q < 4; q++) acc[r][q] = 0.f;

    for (int k0 = 0; k0 < D_; k0 += 32) {
#pragma unroll
        for (int i = 0; i < 8; i++) {
            int e = tid + i * 256;
            int r = e >> 5, c = e & 31;
            sX[r][c] = x[(size_t)(m0 + r) * D_ + k0 + c];
        }
#pragma unroll
        for (int i = 0; i < 16; i++) {
            int e = tid + i * 256;
            int p = e >> 5, c = e & 31;
            sP[c][p] = proto[(size_t)p * (D_ + H_) + k0 + c];
        }
        __syncthreads();
#pragma unroll
        for (int kc = 0; kc < 32; kc++) {
            float4 b4 = *(const float4*)&sP[kc][tx * 4];
#pragma unroll
            for (int r = 0; r < 8; r++) {
                float a = sX[ty * 8 + r][kc];
                acc[r][0] += a * b4.x; acc[r][1] += a * b4.y;
                acc[r][2] += a * b4.z; acc[r][3] += a * b4.w;
            }
        }
        __syncthreads();
    }
#pragma unroll
    for (int r = 0; r < 8; r++) {
        int row = m0 + ty * 8 + r;
        float xs = g_xsq[row];
        float4 o;
        o.x = xs + g_psum[tx*4+0] - 2.f * acc[r][0];
        o.y = xs + g_psum[tx*4+1] - 2.f * acc[r][1];
        o.z = xs + g_psum[tx*4+2] - 2.f * acc[r][2];
        o.w = xs + g_psum[tx*4+3] - 2.f * acc[r][3];
        *(float4*)&g_A[(size_t)row * P_ + tx * 4] = o;
    }
}

// ---------------- counter reset (graph replay determinism) -----------------
__global__ void zero_cnt_kernel() {
    int i = threadIdx.x;
    if (i < 2*16*32) g_cnt[i] = 0;
}

// ---------------- split group barrier --------------------------------------
__device__ __forceinline__ void bar_arrive(unsigned int* cnt) {
    __syncthreads();
    if (threadIdx.x == 0)
        asm volatile("red.release.gpu.global.add.u32 [%0], 1;"
                     :: "l"(cnt) : "memory");
}
__device__ __forceinline__ void bar_wait(unsigned int* cnt, unsigned int target) {
    if (threadIdx.x == 0) {
        unsigned int v;
        do {
            asm volatile("ld.acquire.gpu.global.u32 %0, [%1];"
                         : "=r"(v) : "l"(cnt) : "memory");
        } while (v < target);
    }
    __syncthreads();
}

// ---------------- main persistent recurrent kernel -------------------------
// smem floats: s_pH 16*260 | s_W 128*128 | s_h 16*260 | s_kT2 128*36
#define SMEM_FLOATS (4160 + 16384 + 4160 + 4608)

__global__ void __launch_bounds__(NTHR, 1)
qlstm_main(const float* __restrict__ proto,
           const float* __restrict__ Wf_, const float* __restrict__ bf_,
           const float* __restrict__ Wi_, const float* __restrict__ bi_,
           const float* __restrict__ Wg_, const float* __restrict__ bg_,
           const float* __restrict__ Wo_, const float* __restrict__ bo_,
           float* __restrict__ out) {
    extern __shared__ float sm[];
    float* s_pH  = sm;                    // 16*260
    float* s_W   = s_pH + 16 * 260;       // [p][unit*4+gate]
    float* s_h   = s_W + 128 * 128;       // [16][260]
    float* s_kT2 = s_h + 16 * 260;        // [p][b][2] duplicated, pitch 36

    const int tid = threadIdx.x;
    const int bid = blockIdx.x;
    const int bt  = bid >> 3;   // batch tile 0..15
    const int sub = bid & 7;    // p-tile (phase1) / unit-chunk (phase2)

    const int w    = tid >> 5;
    const int lane = tid & 31;
    // phase-1 mapping: warp tile = 8 b rows x 4 p cols
    const int bl1 = ((w >> 2) << 3) + (lane >> 2);   // 0..15
    const int pl1 = ((w & 3) << 2) + (lane & 3);     // 0..15
    // phase-2 mapping: warp covers 8 units x 8 rows; lane = 2 rows x 1 unit
    const int rh   = w >> 2;
    const int uq   = w & 3;
    const int unit = uq * 8 + (lane & 7);
    const int rr   = lane >> 3;
    const int row0 = rh * 8 + rr * 2;     // even
    const int gu   = sub * 32 + unit;
    const int idx0 = (bt * 16 + row0) * H_ + gu;
    const int idx1 = idx0 + H_;

    // ---- persistent SMEM fills ----
    for (int i = tid; i < 16 * 256; i += NTHR) {
        int pl = i >> 8, j = i & 255;
        s_pH[pl * 260 + j] = proto[(size_t)(sub * 16 + pl) * (D_ + H_) + D_ + j];
    }
#pragma unroll
    for (int g = 0; g < 4; g++) {
        const float* Wp = (g == 0) ? Wf_ : (g == 1) ? Wi_ : (g == 2) ? Wg_ : Wo_;
        for (int i = tid; i < 128 * 32; i += NTHR) {
            int p = i & 127, ul = i >> 7;
            s_W[p * 128 + ul * 4 + g] = Wp[(size_t)(sub * 32 + ul) * P_ + p];
        }
    }
    const ull bfi = pack2(bf_[gu], bi_[gu]);
    const ull bgo = pack2(bg_[gu], bo_[gu]);

    float c0 = 0.f, c1 = 0.f, h0v = 0.f, h1v = 0.f;
    g_h[idx0] = 0.f;
    g_h[idx1] = 0.f;

    unsigned int* k_cnt = &g_cnt[(0 * 16 + bt) * 32];
    unsigned int* h_cnt = &g_cnt[(1 * 16 + bt) * 32];

    const size_t OUT_H = (size_t)T_ * BH_;
    const size_t a_base = (size_t)(bt * 16 + bl1) * P_ + sub * 16 + pl1;
    float* gkg = g_kT + bt * 2048;        // this group's k tile [128][16]

    bar_arrive(h_cnt);
    float a_cur = __ldcg(&g_A[a_base]);   // prefetch in barrier shadow
    bar_wait(h_cnt, 8u);                  // h/c zeros visible in group

#pragma unroll 1
    for (int t = 0; t < T_; t++) {
        // ================= phase 1: k tile (16 b x 16 p) =================
        {
            const float4* gh4 = (const float4*)g_h;
            for (int i = tid; i < 1024; i += NTHR) {
                int b = i >> 6, q = i & 63;
                float4 v = __ldcg(&gh4[(size_t)(bt * 16 + b) * 64 + q]);
                *(float4*)&s_h[b * 260 + q * 4] = v;
            }
            __syncthreads();

            // fused dot(h,pH) and ||h||^2, packed f32x2
            ull da = 0ull, db = 0ull, ha = 0ull, hb = 0ull;
            const float* hp = &s_h[bl1 * 260];
            const float* pp = &s_pH[pl1 * 260];
#pragma unroll 8
            for (int j = 0; j < 256; j += 4) {
                ulonglong2 hv = *(const ulonglong2*)(hp + j);
                ulonglong2 pv = *(const ulonglong2*)(pp + j);
                da = fma2(hv.x, pv.x, da);
                db = fma2(hv.y, pv.y, db);
                ha = fma2(hv.x, hv.x, ha);
                hb = fma2(hv.y, hv.y, hb);
            }
            float dx, dy, dz, dw, qx, qy, qz, qw;
            unpack2(da, dx, dy); unpack2(db, dz, dw);
            unpack2(ha, qx, qy); unpack2(hb, qz, qw);
            float dot = (dx + dy) + (dz + dw);
            float hh  = (qx + qy) + (qz + qw);
            float d2 = a_cur + hh - 2.f * dot;
            gkg[(sub * 16 + pl1) * 16 + bl1] = __expf(-d2);
        }
        bar_arrive(k_cnt);
        {   // barrier shadow: prefetch next A
            int tn = (t + 1 < T_) ? (t + 1) : (T_ - 1);
            a_cur = __ldcg(&g_A[(size_t)tn * B_ * P_ + a_base]);
        }
        bar_wait(k_cnt, 8u * (unsigned)(t + 1));

        // ================= phase 2: gates + state update =================
        {
            // duplicate k into s_kT2 [p][b][2], pitch 36 floats
            const float4* gk4 = (const float4*)gkg;
#pragma unroll
            for (int i = tid; i < 512; i += NTHR) {
                int p = i >> 2, b4 = (i & 3) * 4;
                float4 v = __ldcg(&gk4[p * 4 + (i & 3)]);
                float* dst = &s_kT2[p * 36 + b4 * 2];
                ((float4*)dst)[0] = make_float4(v.x, v.x, v.y, v.y);
                ((float4*)dst)[1] = make_float4(v.z, v.z, v.w, v.w);
            }
            __syncthreads();

            ull afi0 = bfi, ago0 = bgo, afi1 = bfi, ago1 = bgo;
            const float* kbase = &s_kT2[row0 * 2];
#pragma unroll 8
            for (int p = 0; p < 128; p++) {
                ulonglong2 w2 = *(const ulonglong2*)&s_W[p * 128 + unit * 4];
                ulonglong2 kk = *(const ulonglong2*)(kbase + p * 36);
                afi0 = fma2(kk.x, w2.x, afi0);
                ago0 = fma2(kk.x, w2.y, ago0);
                afi1 = fma2(kk.y, w2.x, afi1);
                ago1 = fma2(kk.y, w2.y, ago1);
            }
            float vf, vi, vg, vo;
            unpack2(afi0, vf, vi); unpack2(ago0, vg, vo);
            {
                float f = sigf(vf), ii = sigf(vi), gg = tanh_fast(vg), o = sigf(vo);
                c0 = f * c0 + ii * gg;
                h0v = o * tanh_fast(c0);
                g_h[idx0] = h0v;
            }
            unpack2(afi1, vf, vi); unpack2(ago1, vg, vo);
            {
                float f = sigf(vf), ii = sigf(vi), gg = tanh_fast(vg), o = sigf(vo);
                c1 = f * c1 + ii * gg;
                h1v = o * tanh_fast(c1);
                g_h[idx1] = h1v;
            }
        }
        bar_arrive(h_cnt);
        // barrier shadow: coalesced store of out[t-1] from s_h (h(t-1))
        if (t > 0 && tid < 128) {
            int r = sub * 2 + (tid >> 6);          // 2 rows per block
            int c4 = (tid & 63) * 4;
            float4 v = *(const float4*)&s_h[r * 260 + c4];
            *(float4*)&out[(size_t)(t - 1) * BH_ + (bt * 16 + r) * H_ + c4] = v;
        }
        bar_wait(h_cnt, 8u * (unsigned)(t + 2));
    }

    // final step outputs + hx/cx from registers
    out[(size_t)(T_ - 1) * BH_ + idx0] = h0v;
    out[(size_t)(T_ - 1) * BH_ + idx1] = h1v;
    out[OUT_H + idx0] = h0v;
    out[OUT_H + BH_ + idx0] = c0;
    out[OUT_H + idx1] = h1v;
    out[OUT_H + BH_ + idx1] = c1;
}

// ---------------- launch ----------------------------------------------------
extern "C" void kernel_launch(void* const* d_in, const int* in_sizes, int n_in,
                              void* d_out, int out_size) {
    const float* x     = (const float*)d_in[0];
    const float* proto = (const float*)d_in[1];
    const float* Wf    = (const float*)d_in[2];
    const float* bf    = (const float*)d_in[3];
    const float* Wi    = (const float*)d_in[4];
    const float* bi    = (const float*)d_in[5];
    const float* Wg    = (const float*)d_in[6];
    const float* bg    = (const float*)d_in[7];
    const float* Wo    = (const float*)d_in[8];
    const float* bo    = (const float*)d_in[9];
    float* out = (float*)d_out;

    const int smem_bytes = SMEM_FLOATS * (int)sizeof(float);
    cudaFuncSetAttribute(qlstm_main, cudaFuncAttributeMaxDynamicSharedMemorySize,
                         smem_bytes);

    zero_cnt_kernel<<<1, 1024>>>();
    xsq_kernel<<<M_ / 8, 256>>>(x);
    psum_kernel<<<1, 128>>>(proto);
    agemm_kernel<<<M_ / 64, 256>>>(x, proto);
    qlstm_main<<<NBLK, NTHR, smem_bytes>>>(proto, Wf, bf, Wi, bi, Wg, bg, Wo, bo, out);
}

// round 7
// speedup vs baseline: 1.8985x; 1.2071x over previous
#include <cuda_runtime.h>
#include <cstdint>

#define T_ 512
#define B_ 256
#define D_ 128
#define H_ 256
#define P_ 128
#define M_ (T_*B_)
#define NBLK 128
#define NTHR 256
#define BH_ (B_*H_)

typedef unsigned long long ull;

// ---------------- scratch ---------------------------------------------------
__device__ float g_A[(size_t)T_*B_*P_];          // precomputed x-part of distance
__device__ float g_xsq[M_];
__device__ float g_psum[P_];
__device__ float g_part[2*16*8*128*16];          // double-buffered partial dots
__device__ float g_hsq[2*16*8*16];               // double-buffered partial |h|^2
__device__ unsigned int g_cnt[16*32];            // 1 barrier counter per group

// ---------------- f32x2 helpers --------------------------------------------
__device__ __forceinline__ ull pack2(float lo, float hi) {
    ull r; asm("mov.b64 %0, {%1, %2};" : "=l"(r) : "f"(lo), "f"(hi)); return r;
}
__device__ __forceinline__ void unpack2(ull v, float& lo, float& hi) {
    asm("mov.b64 {%0, %1}, %2;" : "=f"(lo), "=f"(hi) : "l"(v));
}
__device__ __forceinline__ ull fma2(ull a, ull b, ull c) {
    ull d; asm("fma.rn.f32x2 %0, %1, %2, %3;" : "=l"(d) : "l"(a), "l"(b), "l"(c));
    return d;
}
__device__ __forceinline__ float sigf(float x) {
    return __fdividef(1.f, 1.f + __expf(-x));
}
__device__ __forceinline__ float tanh_fast(float x) {
    float e = __expf(2.f * x);
    return 1.f - __fdividef(2.f, e + 1.f);
}

// ---------------- precompute: row norms of x -------------------------------
__global__ void xsq_kernel(const float* __restrict__ x) {
    int warp = (blockIdx.x * blockDim.x + threadIdx.x) >> 5;
    int lane = threadIdx.x & 31;
    if (warp >= M_) return;
    const float* row = x + (size_t)warp * D_;
    float s = 0.f;
#pragma unroll
    for (int i = 0; i < 4; i++) { float v = row[lane + 32*i]; s += v*v; }
#pragma unroll
    for (int o = 16; o; o >>= 1) s += __shfl_down_sync(0xffffffffu, s, o);
    if (lane == 0) g_xsq[warp] = s;
}

// ---------------- precompute: full row norms of prototypes -----------------
__global__ void psum_kernel(const float* __restrict__ proto) {
    int p = threadIdx.x;
    if (p >= P_) return;
    const float* row = proto + (size_t)p * (D_ + H_);
    float s = 0.f;
    for (int i = 0; i < D_ + H_; i++) { float v = row[i]; s += v*v; }
    g_psum[p] = s;
}

// ---------------- precompute GEMM: A[t,b,p] = xsq + psum - 2*x.px ----------
__global__ void agemm_kernel(const float* __restrict__ x,
                             const float* __restrict__ proto) {
    __shared__ float sX[64][33];
    __shared__ float sP[32][132];
    const int tid = threadIdx.x;
    const int tx = tid & 31;
    const int ty = tid >> 5;
    const int m0 = blockIdx.x * 64;

    float acc[8][4];
#pragma unroll
    for (int r = 0; r < 8; r++)
#pragma unroll
        for (int q = 0; q < 4; q++) acc[r][q] = 0.f;

    for (int k0 = 0; k0 < D_; k0 += 32) {
#pragma unroll
        for (int i = 0; i < 8; i++) {
            int e = tid + i * 256;
            int r = e >> 5, c = e & 31;
            sX[r][c] = x[(size_t)(m0 + r) * D_ + k0 + c];
        }
#pragma unroll
        for (int i = 0; i < 16; i++) {
            int e = tid + i * 256;
            int p = e >> 5, c = e & 31;
            sP[c][p] = proto[(size_t)p * (D_ + H_) + k0 + c];
        }
        __syncthreads();
#pragma unroll
        for (int kc = 0; kc < 32; kc++) {
            float4 b4 = *(const float4*)&sP[kc][tx * 4];
#pragma unroll
            for (int r = 0; r < 8; r++) {
                float a = sX[ty * 8 + r][kc];
                acc[r][0] += a * b4.x; acc[r][1] += a * b4.y;
                acc[r][2] += a * b4.z; acc[r][3] += a * b4.w;
            }
        }
        __syncthreads();
    }
#pragma unroll
    for (int r = 0; r < 8; r++) {
        int row = m0 + ty * 8 + r;
        float xs = g_xsq[row];
        float4 o;
        o.x = xs + g_psum[tx*4+0] - 2.f * acc[r][0];
        o.y = xs + g_psum[tx*4+1] - 2.f * acc[r][1];
        o.z = xs + g_psum[tx*4+2] - 2.f * acc[r][2];
        o.w = xs + g_psum[tx*4+3] - 2.f * acc[r][3];
        *(float4*)&g_A[(size_t)row * P_ + tx * 4] = o;
    }
}

// ---------------- counter reset (graph replay determinism) -----------------
__global__ void zero_cnt_kernel() {
    int i = threadIdx.x;
    if (i < 16*32) g_cnt[i] = 0;
}

// ---------------- split group barrier --------------------------------------
__device__ __forceinline__ void bar_arrive(unsigned int* cnt) {
    __syncthreads();
    if (threadIdx.x == 0)
        asm volatile("red.release.gpu.global.add.u32 [%0], 1;"
                     :: "l"(cnt) : "memory");
}
__device__ __forceinline__ void bar_wait(unsigned int* cnt, unsigned int target) {
    if (threadIdx.x == 0) {
        unsigned int v;
        do {
            asm volatile("ld.acquire.gpu.global.u32 %0, [%1];"
                         : "=r"(v) : "l"(cnt) : "memory");
        } while (v < target);
    }
    __syncthreads();
}

// ---------------- main persistent recurrent kernel -------------------------
// smem floats: s_pH 128*36 | s_W 128*128 | s_h 16*36 | s_kT2 128*36 | s_hsqs 16
#define SMEM_FLOATS (4608 + 16384 + 576 + 4608 + 16)

__global__ void __launch_bounds__(NTHR, 1)
qlstm_main(const float* __restrict__ proto,
           const float* __restrict__ Wf_, const float* __restrict__ bf_,
           const float* __restrict__ Wi_, const float* __restrict__ bi_,
           const float* __restrict__ Wg_, const float* __restrict__ bg_,
           const float* __restrict__ Wo_, const float* __restrict__ bo_,
           float* __restrict__ out) {
    extern __shared__ float sm[];
    float* s_pH   = sm;                    // [128 p][36] own-j slice of protoH
    float* s_W    = s_pH + 128 * 36;       // [p][unit*4+gate]
    float* s_h    = s_W + 128 * 128;       // [16 b][36] own-j slice of h (local!)
    float* s_kT2  = s_h + 16 * 36;         // [p][b][2] duplicated k, pitch 36
    float* s_hsqs = s_kT2 + 128 * 36;      // [16] reduced |h|^2

    const int tid = threadIdx.x;
    const int bid = blockIdx.x;
    const int bt  = bid >> 3;   // batch group 0..15
    const int sub = bid & 7;    // j-chunk (phase1) / unit-chunk (phase2)

    // phase-1 / reduce mapping: thread -> (p, 8 b's)
    const int p1p = tid >> 1;          // 0..127
    const int bh  = tid & 1;           // 0/1 -> b = bh*8 + q
    // phase-2 mapping: warp covers 8 units x 8 rows; lane = 2 rows x 1 unit
    const int w    = tid >> 5;
    const int lane = tid & 31;
    const int rh   = w >> 2;
    const int uq   = w & 3;
    const int unit = uq * 8 + (lane & 7);
    const int rr   = lane >> 3;
    const int row0 = rh * 8 + rr * 2;     // even
    const int gu   = sub * 32 + unit;
    const int idx0 = (bt * 16 + row0) * H_ + gu;
    const int idx1 = idx0 + H_;

    // ---- persistent SMEM fills ----
    // pH slice: [p][j_local] = proto[p][128 + sub*32 + j]
    for (int i = tid; i < 128 * 32; i += NTHR) {
        int p = i >> 5, j = i & 31;
        s_pH[p * 36 + j] = proto[(size_t)p * (D_ + H_) + D_ + sub * 32 + j];
    }
#pragma unroll
    for (int g = 0; g < 4; g++) {
        const float* Wp = (g == 0) ? Wf_ : (g == 1) ? Wi_ : (g == 2) ? Wg_ : Wo_;
        for (int i = tid; i < 128 * 32; i += NTHR) {
            int p = i & 127, ul = i >> 7;
            s_W[p * 128 + ul * 4 + g] = Wp[(size_t)(sub * 32 + ul) * P_ + p];
        }
    }
    for (int i = tid; i < 16 * 36; i += NTHR) s_h[i] = 0.f;
    const ull bfi = pack2(bf_[gu], bi_[gu]);
    const ull bgo = pack2(bg_[gu], bo_[gu]);

    float c0 = 0.f, c1 = 0.f, h0v = 0.f, h1v = 0.f;

    unsigned int* cnt = &g_cnt[bt * 32];
    const size_t OUT_H = (size_t)T_ * BH_;

    // prefetch A(0) for this thread's (p, 8 b's)
    float a_cur[8];
#pragma unroll
    for (int q = 0; q < 8; q++)
        a_cur[q] = __ldcg(&g_A[(size_t)(bt * 16 + bh * 8 + q) * P_ + p1p]);

    __syncthreads();

#pragma unroll 1
    for (int t = 0; t < T_; t++) {
        const int buf = t & 1;
        float dsum[8];
#pragma unroll
        for (int q = 0; q < 8; q++) dsum[q] = 0.f;
        float hq = 0.f;

        if (t > 0) {
            // ===== phase 1: partial dots over own 32 j's, all 128 p =====
            {
                ull ph[16];
                const ulonglong2* pr = (const ulonglong2*)&s_pH[p1p * 36];
#pragma unroll
                for (int q = 0; q < 8; q++) {
                    ulonglong2 v = pr[q];
                    ph[2*q] = v.x; ph[2*q+1] = v.y;
                }
                float part[8];
#pragma unroll
                for (int bb = 0; bb < 8; bb++) {
                    const ulonglong2* hr =
                        (const ulonglong2*)&s_h[(bh * 8 + bb) * 36];
                    ull a0 = 0ull, a1 = 0ull;
#pragma unroll
                    for (int q = 0; q < 8; q++) {
                        ulonglong2 hv = hr[q];
                        a0 = fma2(hv.x, ph[2*q],   a0);
                        a1 = fma2(hv.y, ph[2*q+1], a1);
                    }
                    float x0, x1, x2, x3;
                    unpack2(a0, x0, x1); unpack2(a1, x2, x3);
                    part[bb] = (x0 + x1) + (x2 + x3);
                }
                float4* dst = (float4*)&g_part[((((size_t)buf*16 + bt)*8 + sub)*128
                                                + p1p)*16 + bh*8];
                dst[0] = make_float4(part[0], part[1], part[2], part[3]);
                dst[1] = make_float4(part[4], part[5], part[6], part[7]);
            }
            // ===== partial |h|^2 over own j =====
            {
                int hb = tid >> 4, hj = (tid & 15) * 2;
                float v0 = s_h[hb * 36 + hj], v1 = s_h[hb * 36 + hj + 1];
                float ss = v0 * v0 + v1 * v1;
#pragma unroll
                for (int o = 8; o; o >>= 1)
                    ss += __shfl_down_sync(0xffffffffu, ss, o, 16);
                if ((tid & 15) == 0)
                    g_hsq[(((size_t)buf*16 + bt)*8 + sub)*16 + hb] = ss;
            }
            bar_arrive(cnt);
            bar_wait(cnt, 8u * (unsigned)t);

            // ===== reduce: sum 8 partial slices (coalesced, MLP-batched) =====
            {
                const float* base = &g_part[(((size_t)buf*16 + bt)*8)*128*16];
                float4 u[8], v[8];
#pragma unroll
                for (int s = 0; s < 8; s++) {
                    const float4* src =
                        (const float4*)(base + ((size_t)s*128 + p1p)*16 + bh*8);
                    u[s] = __ldcg(&src[0]);
                    v[s] = __ldcg(&src[1]);
                }
#pragma unroll
                for (int s = 0; s < 8; s++) {
                    dsum[0] += u[s].x; dsum[1] += u[s].y;
                    dsum[2] += u[s].z; dsum[3] += u[s].w;
                    dsum[4] += v[s].x; dsum[5] += v[s].y;
                    dsum[6] += v[s].z; dsum[7] += v[s].w;
                }
            }
            if (tid < 16) {
                const float* hb = &g_hsq[(((size_t)buf*16 + bt)*8)*16 + tid];
                float hs = 0.f;
#pragma unroll
                for (int s = 0; s < 8; s++) hs += __ldcg(&hb[s * 16]);
                s_hsqs[tid] = hs;
            }
            __syncthreads();   // s_hsqs ready; also orders s_kT2 reuse
        }

        // ===== assemble k and write duplicated layout =====
        {
            float kv[8];
#pragma unroll
            for (int q = 0; q < 8; q++) {
                float d2 = (t > 0)
                    ? (a_cur[q] + s_hsqs[bh * 8 + q] - 2.f * dsum[q])
                    : a_cur[q];
                kv[q] = __expf(-d2);
            }
            float4* dst = (float4*)&s_kT2[p1p * 36 + bh * 16];
            dst[0] = make_float4(kv[0], kv[0], kv[1], kv[1]);
            dst[1] = make_float4(kv[2], kv[2], kv[3], kv[3]);
            dst[2] = make_float4(kv[4], kv[4], kv[5], kv[5]);
            dst[3] = make_float4(kv[6], kv[6], kv[7], kv[7]);
        }
        // prefetch A(t+1) — latency hidden under the GEMM
        {
            int tn = (t + 1 < T_) ? (t + 1) : (T_ - 1);
#pragma unroll
            for (int q = 0; q < 8; q++)
                a_cur[q] = __ldcg(&g_A[(size_t)tn * B_ * P_ +
                                       (size_t)(bt * 16 + bh * 8 + q) * P_ + p1p]);
        }
        __syncthreads();

        // ===== phase 2: gate GEMM + state update (h stays local) =====
        {
            ull afi0 = bfi, ago0 = bgo, afi1 = bfi, ago1 = bgo;
            const float* kbase = &s_kT2[row0 * 2];
#pragma unroll 8
            for (int p = 0; p < 128; p++) {
                ulonglong2 w2 = *(const ulonglong2*)&s_W[p * 128 + unit * 4];
                ulonglong2 kk = *(const ulonglong2*)(kbase + p * 36);
                afi0 = fma2(kk.x, w2.x, afi0);
                ago0 = fma2(kk.x, w2.y, ago0);
                afi1 = fma2(kk.y, w2.x, afi1);
                ago1 = fma2(kk.y, w2.y, ago1);
            }
            float vf, vi, vg, vo;
            unpack2(afi0, vf, vi); unpack2(ago0, vg, vo);
            {
                float f = sigf(vf), ii = sigf(vi), gg = tanh_fast(vg), o = sigf(vo);
                c0 = f * c0 + ii * gg;
                h0v = o * tanh_fast(c0);
                s_h[row0 * 36 + unit] = h0v;
            }
            unpack2(afi1, vf, vi); unpack2(ago1, vg, vo);
            {
                float f = sigf(vf), ii = sigf(vi), gg = tanh_fast(vg), o = sigf(vo);
                c1 = f * c1 + ii * gg;
                h1v = o * tanh_fast(c1);
                s_h[(row0 + 1) * 36 + unit] = h1v;
            }
            out[(size_t)t * BH_ + idx0] = h0v;
            out[(size_t)t * BH_ + idx1] = h1v;
        }
        __syncthreads();   // h complete before next phase1 reads s_h
    }

    // final hx / cx
    out[OUT_H + idx0] = h0v;
    out[OUT_H + BH_ + idx0] = c0;
    out[OUT_H + idx1] = h1v;
    out[OUT_H + BH_ + idx1] = c1;
}

// ---------------- launch ----------------------------------------------------
extern "C" void kernel_launch(void* const* d_in, const int* in_sizes, int n_in,
                              void* d_out, int out_size) {
    const float* x     = (const float*)d_in[0];
    const float* proto = (const float*)d_in[1];
    const float* Wf    = (const float*)d_in[2];
    const float* bf    = (const float*)d_in[3];
    const float* Wi    = (const float*)d_in[4];
    const float* bi    = (const float*)d_in[5];
    const float* Wg    = (const float*)d_in[6];
    const float* bg    = (const float*)d_in[7];
    const float* Wo    = (const float*)d_in[8];
    const float* bo    = (const float*)d_in[9];
    float* out = (float*)d_out;

    const int smem_bytes = SMEM_FLOATS * (int)sizeof(float);
    cudaFuncSetAttribute(qlstm_main, cudaFuncAttributeMaxDynamicSharedMemorySize,
                         smem_bytes);

    zero_cnt_kernel<<<1, 512>>>();
    xsq_kernel<<<M_ / 8, 256>>>(x);
    psum_kernel<<<1, 128>>>(proto);
    agemm_kernel<<<M_ / 64, 256>>>(x, proto);
    qlstm_main<<<NBLK, NTHR, smem_bytes>>>(proto, Wf, bf, Wi, bi, Wg, bg, Wo, bo, out);
}

// round 8
// speedup vs baseline: 2.2036x; 1.1607x over previous
#include <cuda_runtime.h>
#include <cstdint>

#define T_ 512
#define B_ 256
#define D_ 128
#define H_ 256
#define P_ 128
#define M_ (T_*B_)
#define NBLK 128
#define NTHR 256
#define BH_ (B_*H_)
#define NGRP 32           // 32 groups x 4 blocks, 8 batch rows each
#define GBLK 4

typedef unsigned long long ull;

// ---------------- scratch ---------------------------------------------------
__device__ float g_A[(size_t)T_*B_*P_];          // precomputed x-part of distance
__device__ float g_xsq[M_];
__device__ float g_psum[P_];
__device__ float g_part[2*NGRP*GBLK*128*8];      // double-buffered partial dots
__device__ float g_hsq[2*NGRP*GBLK*8];           // double-buffered partial |h|^2
__device__ unsigned int g_cnt[NGRP*32];          // 1 barrier counter per group

// ---------------- f32x2 helpers --------------------------------------------
__device__ __forceinline__ ull pack2(float lo, float hi) {
    ull r; asm("mov.b64 %0, {%1, %2};" : "=l"(r) : "f"(lo), "f"(hi)); return r;
}
__device__ __forceinline__ void unpack2(ull v, float& lo, float& hi) {
    asm("mov.b64 {%0, %1}, %2;" : "=f"(lo), "=f"(hi) : "l"(v));
}
__device__ __forceinline__ ull fma2(ull a, ull b, ull c) {
    ull d; asm("fma.rn.f32x2 %0, %1, %2, %3;" : "=l"(d) : "l"(a), "l"(b), "l"(c));
    return d;
}
__device__ __forceinline__ float sigf(float x) {
    return __fdividef(1.f, 1.f + __expf(-x));
}
__device__ __forceinline__ float tanh_fast(float x) {
    float e = __expf(2.f * x);
    return 1.f - __fdividef(2.f, e + 1.f);
}

// ---------------- precompute: row norms of x -------------------------------
__global__ void xsq_kernel(const float* __restrict__ x) {
    int warp = (blockIdx.x * blockDim.x + threadIdx.x) >> 5;
    int lane = threadIdx.x & 31;
    if (warp >= M_) return;
    const float* row = x + (size_t)warp * D_;
    float s = 0.f;
#pragma unroll
    for (int i = 0; i < 4; i++) { float v = row[lane + 32*i]; s += v*v; }
#pragma unroll
    for (int o = 16; o; o >>= 1) s += __shfl_down_sync(0xffffffffu, s, o);
    if (lane == 0) g_xsq[warp] = s;
}

// ---------------- precompute: full row norms of prototypes -----------------
__global__ void psum_kernel(const float* __restrict__ proto) {
    int p = threadIdx.x;
    if (p >= P_) return;
    const float* row = proto + (size_t)p * (D_ + H_);
    float s = 0.f;
    for (int i = 0; i < D_ + H_; i++) { float v = row[i]; s += v*v; }
    g_psum[p] = s;
}

// ---------------- precompute GEMM: A[t,b,p] = xsq + psum - 2*x.px ----------
__global__ void agemm_kernel(const float* __restrict__ x,
                             const float* __restrict__ proto) {
    __shared__ float sX[64][33];
    __shared__ float sP[32][132];
    const int tid = threadIdx.x;
    const int tx = tid & 31;
    const int ty = tid >> 5;
    const int m0 = blockIdx.x * 64;

    float acc[8][4];
#pragma unroll
    for (int r = 0; r < 8; r++)
#pragma unroll
        for (int q = 0; q < 4; q++) acc[r][q] = 0.f;

    for (int k0 = 0; k0 < D_; k0 += 32) {
#pragma unroll
        for (int i = 0; i < 8; i++) {
            int e = tid + i * 256;
            int r = e >> 5, c = e & 31;
            sX[r][c] = x[(size_t)(m0 + r) * D_ + k0 + c];
        }
#pragma unroll
        for (int i = 0; i < 16; i++) {
            int e = tid + i * 256;
            int p = e >> 5, c = e & 31;
            sP[c][p] = proto[(size_t)p * (D_ + H_) + k0 + c];
        }
        __syncthreads();
#pragma unroll
        for (int kc = 0; kc < 32; kc++) {
            float4 b4 = *(const float4*)&sP[kc][tx * 4];
#pragma unroll
            for (int r = 0; r < 8; r++) {
                float a = sX[ty * 8 + r][kc];
                acc[r][0] += a * b4.x; acc[r][1] += a * b4.y;
                acc[r][2] += a * b4.z; acc[r][3] += a * b4.w;
            }
        }
        __syncthreads();
    }
#pragma unroll
    for (int r = 0; r < 8; r++) {
        int row = m0 + ty * 8 + r;
        float xs = g_xsq[row];
        float4 o;
        o.x = xs + g_psum[tx*4+0] - 2.f * acc[r][0];
        o.y = xs + g_psum[tx*4+1] - 2.f * acc[r][1];
        o.z = xs + g_psum[tx*4+2] - 2.f * acc[r][2];
        o.w = xs + g_psum[tx*4+3] - 2.f * acc[r][3];
        *(float4*)&g_A[(size_t)row * P_ + tx * 4] = o;
    }
}

// ---------------- counter reset (graph replay determinism) -----------------
__global__ void zero_cnt_kernel() {
    int i = threadIdx.x;
    if (i < NGRP*32) g_cnt[i] = 0;
}

// ---------------- split group barrier --------------------------------------
__device__ __forceinline__ void bar_arrive(unsigned int* cnt) {
    __syncthreads();
    if (threadIdx.x == 0)
        asm volatile("red.release.gpu.global.add.u32 [%0], 1;"
                     :: "l"(cnt) : "memory");
}
__device__ __forceinline__ void bar_wait(unsigned int* cnt, unsigned int target) {
    if (threadIdx.x == 0) {
        unsigned int v;
        do {
            asm volatile("ld.acquire.gpu.global.u32 %0, [%1];"
                         : "=r"(v) : "l"(cnt) : "memory");
        } while (v < target);
    }
    __syncthreads();
}

// ---------------- main persistent recurrent kernel -------------------------
// smem floats: s_pH 128*68 | s_W 128*256 | s_h 8*68 | s_kT2 128*20 | s_hsqs 8
#define SMEM_FLOATS (8704 + 32768 + 544 + 2560 + 8)

__global__ void __launch_bounds__(NTHR, 1)
qlstm_main(const float* __restrict__ proto,
           const float* __restrict__ Wf_, const float* __restrict__ bf_,
           const float* __restrict__ Wi_, const float* __restrict__ bi_,
           const float* __restrict__ Wg_, const float* __restrict__ bg_,
           const float* __restrict__ Wo_, const float* __restrict__ bo_,
           float* __restrict__ out) {
    extern __shared__ float sm[];
    float* s_pH   = sm;                    // [128 p][68] own 64-j slice of protoH
    float* s_W    = s_pH + 128 * 68;       // [p][ul*4+gate], 256 cols
    float* s_h    = s_W + 128 * 256;       // [8 rows][68] own 64-j slice (local!)
    float* s_kT2  = s_h + 8 * 68;          // [p][row*2] duplicated k, pitch 20
    float* s_hsqs = s_kT2 + 128 * 20;      // [8] reduced |h|^2

    const int tid = threadIdx.x;
    const int bid = blockIdx.x;
    const int grp = bid >> 2;   // batch group 0..31 (8 rows each)
    const int sub = bid & 3;    // j-chunk / unit-chunk (64 wide)

    // phase-1 / reduce mapping: thread -> (p, 4 rows)
    const int p1p = tid >> 1;          // 0..127
    const int rh4 = tid & 1;           // rows rh4*4 .. rh4*4+3
    // phase-2 mapping: warp = 8 local units x 4 row-pairs
    const int w    = tid >> 5;
    const int lane = tid & 31;
    const int ul   = w * 8 + (lane & 7);     // local unit 0..63
    const int rp   = lane >> 3;              // 0..3
    const int row0 = rp * 2;                 // even row
    const int gu   = sub * 64 + ul;          // global unit
    const int idx0 = (grp * 8 + row0) * H_ + gu;
    const int idx1 = idx0 + H_;

    // ---- persistent SMEM fills ----
    for (int i = tid; i < 128 * 64; i += NTHR) {
        int p = i >> 6, j = i & 63;
        s_pH[p * 68 + j] = proto[(size_t)p * (D_ + H_) + D_ + sub * 64 + j];
    }
#pragma unroll
    for (int g = 0; g < 4; g++) {
        const float* Wp = (g == 0) ? Wf_ : (g == 1) ? Wi_ : (g == 2) ? Wg_ : Wo_;
        for (int i = tid; i < 128 * 64; i += NTHR) {
            int p = i & 127, u = i >> 7;
            s_W[p * 256 + u * 4 + g] = Wp[(size_t)(sub * 64 + u) * P_ + p];
        }
    }
    for (int i = tid; i < 8 * 68; i += NTHR) s_h[i] = 0.f;
    const ull bfi = pack2(bf_[gu], bi_[gu]);
    const ull bgo = pack2(bg_[gu], bo_[gu]);

    float c0 = 0.f, c1 = 0.f, h0v = 0.f, h1v = 0.f;

    unsigned int* cnt = &g_cnt[grp * 32];
    const size_t OUT_H = (size_t)T_ * BH_;

    // prefetch A(0) for this thread's (p, 4 rows)
    float a_cur[4];
#pragma unroll
    for (int r = 0; r < 4; r++)
        a_cur[r] = __ldcg(&g_A[(size_t)(grp * 8 + rh4 * 4 + r) * P_ + p1p]);

    __syncthreads();

#pragma unroll 1
    for (int t = 0; t < T_; t++) {
        const int buf = t & 1;
        float dsum[4] = {0.f, 0.f, 0.f, 0.f};

        if (t > 0) {
            // ===== phase 1: partial dots over own 64 j's, all 128 p =====
            {
                const ulonglong2* pp = (const ulonglong2*)&s_pH[p1p * 68];
                ull accA[4], accB[4];
#pragma unroll
                for (int r = 0; r < 4; r++) { accA[r] = 0ull; accB[r] = 0ull; }
#pragma unroll 4
                for (int jc = 0; jc < 16; jc++) {
                    ulonglong2 pv = pp[jc];
#pragma unroll
                    for (int r = 0; r < 4; r++) {
                        ulonglong2 hv = *(const ulonglong2*)
                            &s_h[(rh4 * 4 + r) * 68 + jc * 4];
                        accA[r] = fma2(hv.x, pv.x, accA[r]);
                        accB[r] = fma2(hv.y, pv.y, accB[r]);
                    }
                }
                float4 pw;
                float* pwf = (float*)&pw;
#pragma unroll
                for (int r = 0; r < 4; r++) {
                    float x0, x1, x2, x3;
                    unpack2(accA[r], x0, x1);
                    unpack2(accB[r], x2, x3);
                    pwf[r] = (x0 + x1) + (x2 + x3);
                }
                *(float4*)&g_part[((((size_t)buf*NGRP + grp)*GBLK + sub)*128
                                   + p1p)*8 + rh4*4] = pw;
            }
            // ===== partial |h|^2 over own 64 j =====
            if (tid < 64) {
                int row = tid >> 3, seg = (tid & 7) * 8;
                const float* hr = &s_h[row * 68 + seg];
                float ss = 0.f;
#pragma unroll
                for (int j = 0; j < 8; j++) ss += hr[j] * hr[j];
#pragma unroll
                for (int o = 4; o; o >>= 1)
                    ss += __shfl_down_sync(0xffffffffu, ss, o, 8);
                if ((tid & 7) == 0)
                    g_hsq[(((size_t)buf*NGRP + grp)*GBLK + sub)*8 + row] = ss;
            }
            bar_arrive(cnt);
            bar_wait(cnt, 4u * (unsigned)t);

            // ===== reduce: sum 4 partial slices (1 L2 round trip, MLP=4) =====
            {
                const float4* pb = (const float4*)
                    &g_part[(((size_t)buf*NGRP + grp)*GBLK)*1024];
                float4 u0 = __ldcg(&pb[0*256 + p1p*2 + rh4]);
                float4 u1 = __ldcg(&pb[1*256 + p1p*2 + rh4]);
                float4 u2 = __ldcg(&pb[2*256 + p1p*2 + rh4]);
                float4 u3 = __ldcg(&pb[3*256 + p1p*2 + rh4]);
                dsum[0] = (u0.x + u1.x) + (u2.x + u3.x);
                dsum[1] = (u0.y + u1.y) + (u2.y + u3.y);
                dsum[2] = (u0.z + u1.z) + (u2.z + u3.z);
                dsum[3] = (u0.w + u1.w) + (u2.w + u3.w);
            }
            if (tid < 8) {
                const float* hb = &g_hsq[(((size_t)buf*NGRP + grp)*GBLK)*8 + tid];
                float hs = 0.f;
#pragma unroll
                for (int s = 0; s < GBLK; s++) hs += __ldcg(&hb[s * 8]);
                s_hsqs[tid] = hs;
            }
            __syncthreads();   // s_hsqs ready
        }

        // ===== assemble k and write duplicated layout =====
        {
            float kv[4];
#pragma unroll
            for (int r = 0; r < 4; r++) {
                float d2 = (t > 0)
                    ? (a_cur[r] + s_hsqs[rh4 * 4 + r] - 2.f * dsum[r])
                    : a_cur[r];
                kv[r] = __expf(-d2);
            }
            float4* dst = (float4*)&s_kT2[p1p * 20 + rh4 * 8];
            dst[0] = make_float4(kv[0], kv[0], kv[1], kv[1]);
            dst[1] = make_float4(kv[2], kv[2], kv[3], kv[3]);
        }
        // prefetch A(t+1) — latency hidden under the GEMM
        {
            int tn = (t + 1 < T_) ? (t + 1) : (T_ - 1);
#pragma unroll
            for (int r = 0; r < 4; r++)
                a_cur[r] = __ldcg(&g_A[(size_t)tn * B_ * P_ +
                                       (size_t)(grp * 8 + rh4 * 4 + r) * P_ + p1p]);
        }
        __syncthreads();

        // ===== phase 2: gate GEMM + state update (h stays local) =====
        {
            ull afi0 = bfi, ago0 = bgo, afi1 = bfi, ago1 = bgo;
            const float* kbase = &s_kT2[row0 * 2];
            const float* wbase = &s_W[ul * 4];
#pragma unroll 8
            for (int p = 0; p < 128; p++) {
                ulonglong2 w2 = *(const ulonglong2*)(wbase + p * 256);
                ulonglong2 kk = *(const ulonglong2*)(kbase + p * 20);
                afi0 = fma2(kk.x, w2.x, afi0);
                ago0 = fma2(kk.x, w2.y, ago0);
                afi1 = fma2(kk.y, w2.x, afi1);
                ago1 = fma2(kk.y, w2.y, ago1);
            }
            float vf, vi, vg, vo;
            unpack2(afi0, vf, vi); unpack2(ago0, vg, vo);
            {
                float f = sigf(vf), ii = sigf(vi), gg = tanh_fast(vg), o = sigf(vo);
                c0 = f * c0 + ii * gg;
                h0v = o * tanh_fast(c0);
                s_h[row0 * 68 + ul] = h0v;
            }
            unpack2(afi1, vf, vi); unpack2(ago1, vg, vo);
            {
                float f = sigf(vf), ii = sigf(vi), gg = tanh_fast(vg), o = sigf(vo);
                c1 = f * c1 + ii * gg;
                h1v = o * tanh_fast(c1);
                s_h[(row0 + 1) * 68 + ul] = h1v;
            }
            out[(size_t)t * BH_ + idx0] = h0v;
            out[(size_t)t * BH_ + idx1] = h1v;
        }
        __syncthreads();   // h complete before next phase1 reads s_h
    }

    // final hx / cx
    out[OUT_H + idx0] = h0v;
    out[OUT_H + BH_ + idx0] = c0;
    out[OUT_H + idx1] = h1v;
    out[OUT_H + BH_ + idx1] = c1;
}

// ---------------- launch ----------------------------------------------------
extern "C" void kernel_launch(void* const* d_in, const int* in_sizes, int n_in,
                              void* d_out, int out_size) {
    const float* x     = (const float*)d_in[0];
    const float* proto = (const float*)d_in[1];
    const float* Wf    = (const float*)d_in[2];
    const float* bf    = (const float*)d_in[3];
    const float* Wi    = (const float*)d_in[4];
    const float* bi    = (const float*)d_in[5];
    const float* Wg    = (const float*)d_in[6];
    const float* bg    = (const float*)d_in[7];
    const float* Wo    = (const float*)d_in[8];
    const float* bo    = (const float*)d_in[9];
    float* out = (float*)d_out;

    const int smem_bytes = SMEM_FLOATS * (int)sizeof(float);
    cudaFuncSetAttribute(qlstm_main, cudaFuncAttributeMaxDynamicSharedMemorySize,
                         smem_bytes);

    zero_cnt_kernel<<<1, 1024>>>();
    xsq_kernel<<<M_ / 8, 256>>>(x);
    psum_kernel<<<1, 128>>>(proto);
    agemm_kernel<<<M_ / 64, 256>>>(x, proto);
    qlstm_main<<<NBLK, NTHR, smem_bytes>>>(proto, Wf, bf, Wi, bi, Wg, bg, Wo, bo, out);
}